// round 4
// baseline (speedup 1.0000x reference)
#include <cuda_runtime.h>
#include <math_constants.h>

#define NWARP 32

// order-preserving float<->uint transforms (monotonic bijection)
__device__ __forceinline__ unsigned ford(float f) {
    int b = __float_as_int(f);
    return (unsigned)(b ^ ((b >> 31) | 0x80000000));
}
__device__ __forceinline__ float funord(unsigned o) {
    int b = (int)o;
    return __int_as_float(b ^ ((~(b >> 31)) | 0x80000000));
}

// i < 0 sentinel ("row -1") -> -2 ; blank -> -1 ; i>1 -> i-1 ; i==1 -> 0
__device__ __forceinline__ int ctc_char(int i) {
    if (i < 0) return -2;
    return (i == 0) ? -1 : ((i > 1) ? (i - 1) : 0);
}

// Full-warp argmax of one 512-float row. Returns col (to all lanes).
// First-occurrence tie-break.
__device__ __forceinline__ int argmax_row(const float4* __restrict__ p, int lane) {
    const float4 a = __ldg(p + lane);
    const float4 b = __ldg(p + lane + 32);
    const float4 c = __ldg(p + lane + 64);
    const float4 d = __ldg(p + lane + 96);

    // lane-local max, balanced tree (FMNMX pipe, short dep chains)
    const float ma = fmaxf(fmaxf(a.x, a.y), fmaxf(a.z, a.w));
    const float mb = fmaxf(fmaxf(b.x, b.y), fmaxf(b.z, b.w));
    const float mc = fmaxf(fmaxf(c.x, c.y), fmaxf(c.z, c.w));
    const float md = fmaxf(fmaxf(d.x, d.y), fmaxf(d.z, d.w));
    const float m  = fmaxf(fmaxf(ma, mb), fmaxf(mc, md));

    // single-instruction warp max (REDUX.MAX on ordered uint)
    const unsigned wmo = __reduce_max_sync(0xffffffffu, ford(m));
    const float wmax = funord(wmo);

    // lowest column equal to wmax (descending select order -> min col wins)
    const int b0 = lane * 4, b1 = (lane + 32) * 4, b2 = (lane + 64) * 4, b3 = (lane + 96) * 4;
    int cand = 0x7fffffff;
    cand = (d.w == wmax) ? b3 + 3 : cand;
    cand = (d.z == wmax) ? b3 + 2 : cand;
    cand = (d.y == wmax) ? b3 + 1 : cand;
    cand = (d.x == wmax) ? b3 + 0 : cand;
    cand = (c.w == wmax) ? b2 + 3 : cand;
    cand = (c.z == wmax) ? b2 + 2 : cand;
    cand = (c.y == wmax) ? b2 + 1 : cand;
    cand = (c.x == wmax) ? b2 + 0 : cand;
    cand = (b.w == wmax) ? b1 + 3 : cand;
    cand = (b.z == wmax) ? b1 + 2 : cand;
    cand = (b.y == wmax) ? b1 + 1 : cand;
    cand = (b.x == wmax) ? b1 + 0 : cand;
    cand = (a.w == wmax) ? b0 + 3 : cand;
    cand = (a.z == wmax) ? b0 + 2 : cand;
    cand = (a.y == wmax) ? b0 + 1 : cand;
    cand = (a.x == wmax) ? b0 + 0 : cand;

    return (int)__reduce_min_sync(0xffffffffu, (unsigned)cand);
}

// Each block owns a contiguous chunk of rpb rows; processes 32 rows per
// iteration (1 row/warp), carrying the boundary argmax in smem so the keep
// mask needs no cross-block traffic. Only the block's first boundary row
// (one per block) is recomputed redundantly.
__global__ __launch_bounds__(1024, 2)
void ctc_persist_kernel(const float* __restrict__ em,
                        float* __restrict__ out_index,
                        float* __restrict__ out_keep,
                        int T, int rpb) {
    const int w    = threadIdx.x >> 5;
    const int lane = threadIdx.x & 31;
    const int start = blockIdx.x * rpb;
    if (start >= T) return;
    const int end = min(start + rpb, T);

    __shared__ int s_idx[NWARP];
    __shared__ int s_prev;

    // prologue: index of row start-1 (or -1 sentinel)
    if (w == 0) {
        int pv = -1;
        if (start > 0)
            pv = argmax_row(reinterpret_cast<const float4*>(em) + (size_t)(start - 1) * 128, lane);
        if (lane == 0) s_prev = pv;
    }

    for (int r0 = start; r0 < end; r0 += NWARP) {
        const int row = r0 + w;
        int bi = -1;
        if (row < end)
            bi = argmax_row(reinterpret_cast<const float4*>(em) + (size_t)row * 128, lane);
        if (lane == 0) s_idx[w] = bi;
        __syncthreads();

        // coalesced output phase (first warp)
        if (threadIdx.x < NWARP) {
            const int t = r0 + threadIdx.x;
            if (t < end) {
                const int cur = s_idx[threadIdx.x];
                const int prv = (threadIdx.x == 0) ? s_prev : s_idx[threadIdx.x - 1];
                const int c  = ctc_char(cur);
                const int pc = ctc_char(prv);
                out_index[t] = (float)cur;
                out_keep[t]  = (c != pc && c != -1) ? 1.0f : 0.0f;
            }
        }
        __syncthreads();
        if (threadIdx.x == 0) {
            const int last = min(end - r0, NWARP) - 1;
            s_prev = s_idx[last];
        }
        __syncthreads();
    }
}

extern "C" void kernel_launch(void* const* d_in, const int* in_sizes, int n_in,
                              void* d_out, int out_size) {
    const float* emission = (const float*)d_in[0];
    const int V = 512;
    const int T = in_sizes[0] / V;   // 65536

    float* out = (float*)d_out;      // [0:T] index (as float), [T:2T] keep (0/1)
    float* out_index = out;
    float* out_keep  = out + T;

    // ~2 blocks/SM worth of persistent blocks; rpb rounded to 32 for aligned chunks
    const int target_blocks = 296;                           // 2 x 148 SMs
    int rpb = (T + target_blocks - 1) / target_blocks;
    rpb = (rpb + 31) & ~31;                                  // multiple of 32
    const int blocks = (T + rpb - 1) / rpb;

    ctc_persist_kernel<<<blocks, 1024>>>(emission, out_index, out_keep, T, rpb);
}

// round 5
// speedup vs baseline: 1.0694x; 1.0694x over previous
#include <cuda_runtime.h>
#include <math_constants.h>

#define ROWS_OUT 31

// order-preserving float<->uint transforms (monotonic bijection)
__device__ __forceinline__ unsigned ford(float f) {
    int b = __float_as_int(f);
    return (unsigned)(b ^ ((b >> 31) | 0x80000000));
}
__device__ __forceinline__ float funord(unsigned o) {
    int b = (int)o;
    return __int_as_float(b ^ ((~(b >> 31)) | 0x80000000));
}

// i < 0 sentinel ("row -1") -> -2 ; blank -> -1 ; i>1 -> i-1 ; i==1 -> 0
__device__ __forceinline__ int ctc_char(int i) {
    if (i < 0) return -2;
    return (i == 0) ? -1 : ((i > 1) ? (i - 1) : 0);
}

// Full-warp argmax of one 512-float row; result returned to ALL lanes.
// First-occurrence tie-break.
__device__ __forceinline__ int argmax_row(const float4* __restrict__ p, int lane) {
    const float4 a = __ldg(p + lane);
    const float4 b = __ldg(p + lane + 32);
    const float4 c = __ldg(p + lane + 64);
    const float4 d = __ldg(p + lane + 96);

    // lane-local max, balanced tree
    const float ma = fmaxf(fmaxf(a.x, a.y), fmaxf(a.z, a.w));
    const float mb = fmaxf(fmaxf(b.x, b.y), fmaxf(b.z, b.w));
    const float mc = fmaxf(fmaxf(c.x, c.y), fmaxf(c.z, c.w));
    const float md = fmaxf(fmaxf(d.x, d.y), fmaxf(d.z, d.w));
    const float m  = fmaxf(fmaxf(ma, mb), fmaxf(mc, md));

    // single-instruction warp max
    const float wmax = funord(__reduce_max_sync(0xffffffffu, ford(m)));

    // lowest column equal to wmax (descending select order -> min col wins)
    const int b0 = lane * 4, b1 = (lane + 32) * 4, b2 = (lane + 64) * 4, b3 = (lane + 96) * 4;
    int cand = 0x7fffffff;
    cand = (d.w == wmax) ? b3 + 3 : cand;
    cand = (d.z == wmax) ? b3 + 2 : cand;
    cand = (d.y == wmax) ? b3 + 1 : cand;
    cand = (d.x == wmax) ? b3 + 0 : cand;
    cand = (c.w == wmax) ? b2 + 3 : cand;
    cand = (c.z == wmax) ? b2 + 2 : cand;
    cand = (c.y == wmax) ? b2 + 1 : cand;
    cand = (c.x == wmax) ? b2 + 0 : cand;
    cand = (b.w == wmax) ? b1 + 3 : cand;
    cand = (b.z == wmax) ? b1 + 2 : cand;
    cand = (b.y == wmax) ? b1 + 1 : cand;
    cand = (b.x == wmax) ? b1 + 0 : cand;
    cand = (a.w == wmax) ? b0 + 3 : cand;
    cand = (a.z == wmax) ? b0 + 2 : cand;
    cand = (a.y == wmax) ? b0 + 1 : cand;
    cand = (a.x == wmax) ? b0 + 0 : cand;

    return (int)__reduce_min_sync(0xffffffffu, (unsigned)cand);
}

// Block b (32 warps): warp w computes argmax of row 31b - 1 + w (boundary row
// recomputed redundantly). One __syncthreads, then warp 0 writes both outputs
// coalesced.
__global__ __launch_bounds__(1024, 2)
void ctc_fused_kernel(const float* __restrict__ em,
                      float* __restrict__ out_index,
                      float* __restrict__ out_keep,
                      int T) {
    __shared__ int s_idx[32];

    const int w    = threadIdx.x >> 5;
    const int lane = threadIdx.x & 31;
    const int row  = blockIdx.x * ROWS_OUT - 1 + w;

    int bidx = -1;                        // sentinel: row out of range
    if (row >= 0 && row < T)
        bidx = argmax_row(reinterpret_cast<const float4*>(em) + (size_t)row * 128, lane);

    if (lane == 0) s_idx[w] = bidx;
    __syncthreads();

    // coalesced output phase: thread i handles output row 31b + i (i = 0..30)
    if (threadIdx.x < ROWS_OUT) {
        const int t = blockIdx.x * ROWS_OUT + threadIdx.x;
        if (t < T) {
            const int cur = s_idx[threadIdx.x + 1];
            const int prv = s_idx[threadIdx.x];
            const int c  = ctc_char(cur);
            const int pc = ctc_char(prv);
            out_index[t] = (float)cur;
            out_keep[t]  = (c != pc && c != -1) ? 1.0f : 0.0f;
        }
    }
}

extern "C" void kernel_launch(void* const* d_in, const int* in_sizes, int n_in,
                              void* d_out, int out_size) {
    const float* emission = (const float*)d_in[0];
    const int V = 512;
    const int T = in_sizes[0] / V;   // 65536

    float* out = (float*)d_out;      // [0:T] index (as float), [T:2T] keep (0/1)
    float* out_index = out;
    float* out_keep  = out + T;

    const int blocks = (T + ROWS_OUT - 1) / ROWS_OUT;   // 2115
    ctc_fused_kernel<<<blocks, 1024>>>(emission, out_index, out_keep, T);
}

// round 6
// speedup vs baseline: 1.0708x; 1.0013x over previous
#include <cuda_runtime.h>
#include <math_constants.h>

#define ROWS_OUT 31

// order-preserving float<->uint transforms (monotonic bijection)
__device__ __forceinline__ unsigned ford(float f) {
    int b = __float_as_int(f);
    return (unsigned)(b ^ ((b >> 31) | 0x80000000));
}
__device__ __forceinline__ float funord(unsigned o) {
    int b = (int)o;
    return __int_as_float(b ^ ((~(b >> 31)) | 0x80000000));
}

// i < 0 sentinel ("row -1") -> -2 ; blank -> -1 ; i>1 -> i-1 ; i==1 -> 0
__device__ __forceinline__ int ctc_char(int i) {
    if (i < 0) return -2;
    return (i == 0) ? -1 : ((i > 1) ? (i - 1) : 0);
}

// Reduce one already-loaded row (16 floats/lane) to its argmax (all lanes).
// First-occurrence tie-break.
__device__ __forceinline__ int reduce_row(const float4 a, const float4 b,
                                          const float4 c, const float4 d,
                                          int lane) {
    const float ma = fmaxf(fmaxf(a.x, a.y), fmaxf(a.z, a.w));
    const float mb = fmaxf(fmaxf(b.x, b.y), fmaxf(b.z, b.w));
    const float mc = fmaxf(fmaxf(c.x, c.y), fmaxf(c.z, c.w));
    const float md = fmaxf(fmaxf(d.x, d.y), fmaxf(d.z, d.w));
    const float m  = fmaxf(fmaxf(ma, mb), fmaxf(mc, md));

    const float wmax = funord(__reduce_max_sync(0xffffffffu, ford(m)));

    const int b0 = lane * 4, b1 = (lane + 32) * 4, b2 = (lane + 64) * 4, b3 = (lane + 96) * 4;
    int cand = 0x7fffffff;
    cand = (d.w == wmax) ? b3 + 3 : cand;
    cand = (d.z == wmax) ? b3 + 2 : cand;
    cand = (d.y == wmax) ? b3 + 1 : cand;
    cand = (d.x == wmax) ? b3 + 0 : cand;
    cand = (c.w == wmax) ? b2 + 3 : cand;
    cand = (c.z == wmax) ? b2 + 2 : cand;
    cand = (c.y == wmax) ? b2 + 1 : cand;
    cand = (c.x == wmax) ? b2 + 0 : cand;
    cand = (b.w == wmax) ? b1 + 3 : cand;
    cand = (b.z == wmax) ? b1 + 2 : cand;
    cand = (b.y == wmax) ? b1 + 1 : cand;
    cand = (b.x == wmax) ? b1 + 0 : cand;
    cand = (a.w == wmax) ? b0 + 3 : cand;
    cand = (a.z == wmax) ? b0 + 2 : cand;
    cand = (a.y == wmax) ? b0 + 1 : cand;
    cand = (a.x == wmax) ? b0 + 0 : cand;

    return (int)__reduce_min_sync(0xffffffffu, (unsigned)cand);
}

// Block b (16 warps, 512 threads): warp w computes argmax of rows
// 31b - 1 + 2w and 31b + 2w (loads for both front-batched -> MLP 8/warp).
// Boundary row 31b-1 recomputed redundantly. One sync, then warp 0 writes
// both outputs coalesced.
__global__ __launch_bounds__(512, 2)
void ctc_fused_kernel(const float* __restrict__ em,
                      float* __restrict__ out_index,
                      float* __restrict__ out_keep,
                      int T) {
    __shared__ int s_idx[32];

    const int w    = threadIdx.x >> 5;   // 0..15
    const int lane = threadIdx.x & 31;
    const int r0   = blockIdx.x * ROWS_OUT - 1 + 2 * w;
    const int r1   = r0 + 1;

    const bool v0 = (r0 >= 0) && (r0 < T);
    const bool v1 = (r1 < T);            // r1 >= 0 always

    float4 a0, b0, c0, d0, a1, b1, c1, d1;
    const float4* p0 = reinterpret_cast<const float4*>(em) + (size_t)r0 * 128;
    const float4* p1 = reinterpret_cast<const float4*>(em) + (size_t)r1 * 128;

    // front-batched loads: 8 independent LDG.128 per lane
    if (v0) {
        a0 = __ldg(p0 + lane);
        b0 = __ldg(p0 + lane + 32);
        c0 = __ldg(p0 + lane + 64);
        d0 = __ldg(p0 + lane + 96);
    }
    if (v1) {
        a1 = __ldg(p1 + lane);
        b1 = __ldg(p1 + lane + 32);
        c1 = __ldg(p1 + lane + 64);
        d1 = __ldg(p1 + lane + 96);
    }

    int i0 = -1, i1 = -1;
    if (v0) i0 = reduce_row(a0, b0, c0, d0, lane);
    if (v1) i1 = reduce_row(a1, b1, c1, d1, lane);

    if (lane == 0) {
        s_idx[2 * w]     = i0;
        s_idx[2 * w + 1] = i1;
    }
    __syncthreads();

    // coalesced output phase: thread i handles output row 31b + i (i = 0..30)
    if (threadIdx.x < ROWS_OUT) {
        const int t = blockIdx.x * ROWS_OUT + threadIdx.x;
        if (t < T) {
            const int cur = s_idx[threadIdx.x + 1];
            const int prv = s_idx[threadIdx.x];
            const int c  = ctc_char(cur);
            const int pc = ctc_char(prv);
            out_index[t] = (float)cur;
            out_keep[t]  = (c != pc && c != -1) ? 1.0f : 0.0f;
        }
    }
}

extern "C" void kernel_launch(void* const* d_in, const int* in_sizes, int n_in,
                              void* d_out, int out_size) {
    const float* emission = (const float*)d_in[0];
    const int V = 512;
    const int T = in_sizes[0] / V;   // 65536

    float* out = (float*)d_out;      // [0:T] index (as float), [T:2T] keep (0/1)
    float* out_index = out;
    float* out_keep  = out + T;

    const int blocks = (T + ROWS_OUT - 1) / ROWS_OUT;   // 2115
    ctc_fused_kernel<<<blocks, 512>>>(emission, out_index, out_keep, T);
}